// round 11
// baseline (speedup 1.0000x reference)
#include <cuda_runtime.h>

#define TT 8192
#define H 512
#define NCTA_L 64      // CTAs per layer
#define NCTA 128       // total
#define NTHREADS 256
#define HPC 8          // h outputs per CTA
#define PADC 32        // 32 uints = one 128B line per counter
#define D1 8           // h1 ring depth (L0 may run up to D1-1 ahead)
#define FULLMASK 0xffffffffu

// Static scratch (no allocations allowed)
__device__ float g_h1ring[D1][H];    // h1 exchange ring (hot 16KB)
__device__ float g_h2ring[2][H];     // h2 exchange ring (hot 4KB)
__device__ float g_hfinal[H];        // final h2
__device__ unsigned g_barA[8 * PADC];  // layer-0 counters (8 padded lines)
__device__ unsigned g_barB[8 * PADC];  // layer-1 counters

// ---------- helpers ----------
__device__ __forceinline__ unsigned long long pack2(float lo, float hi) {
    unsigned long long r;
    asm("mov.b64 %0,{%1,%2};" : "=l"(r) : "f"(lo), "f"(hi));
    return r;
}
__device__ __forceinline__ void unpack2(unsigned long long v, float& lo, float& hi) {
    asm("mov.b64 {%0,%1},%2;" : "=f"(lo), "=f"(hi) : "l"(v));
}
// packed fp32x2 FMA: 2 MACs per instruction (PTX-only on Blackwell)
__device__ __forceinline__ void fma2(unsigned long long& acc, unsigned long long a, unsigned long long b) {
    asm("fma.rn.f32x2 %0,%1,%2,%0;" : "+l"(acc) : "l"(a), "l"(b));
}
__device__ __forceinline__ float4 ldcg4(const float4* p) {
    float4 v;
    asm volatile("ld.global.cg.v4.f32 {%0,%1,%2,%3},[%4];"
                 : "=f"(v.x), "=f"(v.y), "=f"(v.z), "=f"(v.w) : "l"(p));
    return v;
}
__device__ __forceinline__ unsigned ldacq(const unsigned* p) {
    unsigned v;
    asm volatile("ld.acquire.gpu.u32 %0,[%1];" : "=r"(v) : "l"(p));
    return v;
}
__device__ __forceinline__ float tanhfast(float x) {
    float y; asm("tanh.approx.f32 %0,%1;" : "=f"(y) : "f"(x)); return y;
}
__device__ __forceinline__ float sigfast(float x) { return 0.5f * tanhfast(0.5f * x) + 0.5f; }

// ---------- init: reset both counter sets ----------
__global__ void init_kernel() {
    int t = threadIdx.x;
    if (t < 8 * PADC) { g_barA[t] = 0u; g_barB[t] = 0u; }
}

// ---------- decoupled 2-layer persistent LSTM ----------
// 128 CTAs x 256 threads (single wave). CTAs [0,64): layer 0; [64,128): layer 1.
// Each layer runs its OWN R8-style recurrence (8 padded counters, 8 arrivals each);
// the layers are coupled only by ring flow-control waits that sit off the critical
// path once rates match (L0 runs up to D1-1=7 steps ahead of L1).
// CTA-internal layout (R8): CTA owns 8 outputs -> 32 gate rows; warp w covers
// columns [w*64,(w+1)*64); lane l = local gate row (0..7=i, 8..15=f, 16..23=g, 24..31=o).
__global__ void __launch_bounds__(NTHREADS, 1) lstm2_kernel(
    const float* __restrict__ x,
    const float* __restrict__ wih0, const float* __restrict__ whh0,
    const float* __restrict__ bih0, const float* __restrict__ bhh0,
    const float* __restrict__ wih1, const float* __restrict__ whh1,
    const float* __restrict__ bih1, const float* __restrict__ bhh1)
{
    const int tid = threadIdx.x;
    const int w = tid >> 5;
    const int l = tid & 31;
    const int bg = blockIdx.x;
    const bool is0 = bg < NCTA_L;
    const int b = is0 ? bg : (bg - NCTA_L);
    const int sec = l >> 3;
    const int j8 = l & 7;
    const int grow = sec * H + b * HPC + j8;

    __shared__ float red[8][33];
    __shared__ float sx[TT];
    if (is0) for (int i = tid; i < TT; i += NTHREADS) sx[i] = x[i];

    // recurrent weights -> registers (64 floats/thread)
    unsigned long long whh[32];
    {
        const float* wr = (is0 ? whh0 : whh1) + (size_t)grow * H + w * 64;
#pragma unroll
        for (int k = 0; k < 16; k++) {
            float4 v = *(const float4*)(wr + 4 * k);
            whh[2 * k] = pack2(v.x, v.y);
            whh[2 * k + 1] = pack2(v.z, v.w);
        }
    }
    // layer-1 input weights (L1 CTAs only)
    unsigned long long wihr[32];
    if (!is0) {
        const float* wr = wih1 + (size_t)grow * H + w * 64;
#pragma unroll
        for (int k = 0; k < 16; k++) {
            float4 v = *(const float4*)(wr + 4 * k);
            wihr[2 * k] = pack2(v.x, v.y);
            wihr[2 * k + 1] = pack2(v.z, v.w);
        }
    }
    const float bias = is0 ? (bih0[grow] + bhh0[grow]) : (bih1[grow] + bhh1[grow]);
    const float wx = is0 ? wih0[grow] : 0.0f;   // NC = 1
    float c = 0.0f;                              // cell state (lanes 0..7 of warp 0)
    __syncthreads();

    for (int t = 0; t < TT; t++) {
        // ---- combined wait (single poll loop; lanes 0..7 watch counter set 1,
        //      lanes 8..15 watch counter set 2, lanes 16..31 pass)
        {
            bool act; unsigned tgt; const unsigned* cp;
            if (is0) {
                // own recurrence: h1(t-1) published by all L0 -> barA >= 8*t
                // ring safety:   L1 consumed h1(t-D1)       -> barB >= 8*(t-D1+1)
                if (l < 8)       { act = (t > 0);   tgt = 8u * (unsigned)t;            cp = &g_barA[l * PADC]; }
                else if (l < 16) { act = (t >= D1); tgt = 8u * (unsigned)(t - D1 + 1); cp = &g_barB[(l - 8) * PADC]; }
                else             { act = false;     tgt = 0u;                          cp = &g_barA[0]; }
            } else {
                // input ready:   h1(t) published by all L0  -> barA >= 8*(t+1)
                // own recurrence: h2(t-1) published by all L1 -> barB >= 8*t
                if (l < 8)       { act = true;      tgt = 8u * (unsigned)(t + 1);      cp = &g_barA[l * PADC]; }
                else if (l < 16) { act = (t > 0);   tgt = 8u * (unsigned)t;            cp = &g_barB[(l - 8) * PADC]; }
                else             { act = false;     tgt = 0u;                          cp = &g_barA[0]; }
            }
            if (tid < 32) {
                if (__any_sync(FULLMASK, act)) {
                    for (;;) {
                        unsigned v = act ? ldacq(cp) : tgt;
                        if (__all_sync(FULLMASK, v >= tgt)) break;
                    }
                }
            }
            __syncthreads();
        }

        // ---- mat-vec
        unsigned long long a0 = 0ull, a1 = 0ull;
        if (is0) {
            if (t > 0) {
                const float4* hb = ((const float4*)g_h1ring[(t - 1) & (D1 - 1)]) + w * 16;
#pragma unroll
                for (int k = 0; k < 16; k++) {
                    float4 hv = ldcg4(hb + k);
                    fma2(a0, whh[2 * k], pack2(hv.x, hv.y));
                    fma2(a1, whh[2 * k + 1], pack2(hv.z, hv.w));
                }
            }
        } else {
            {   // W_ih1 . h1(t)
                const float4* hb = ((const float4*)g_h1ring[t & (D1 - 1)]) + w * 16;
#pragma unroll
                for (int k = 0; k < 16; k++) {
                    float4 hv = ldcg4(hb + k);
                    fma2(a0, wihr[2 * k], pack2(hv.x, hv.y));
                    fma2(a1, wihr[2 * k + 1], pack2(hv.z, hv.w));
                }
            }
            if (t > 0) {   // W_hh1 . h2(t-1)
                const float4* hb = ((const float4*)g_h2ring[(t - 1) & 1]) + w * 16;
#pragma unroll
                for (int k = 0; k < 16; k++) {
                    float4 hv = ldcg4(hb + k);
                    fma2(a0, whh[2 * k], pack2(hv.x, hv.y));
                    fma2(a1, whh[2 * k + 1], pack2(hv.z, hv.w));
                }
            }
        }
        float lo0, hi0, lo1, hi1;
        unpack2(a0, lo0, hi0);
        unpack2(a1, lo1, hi1);
        red[w][l] = (lo0 + hi0) + (lo1 + hi1);
        __syncthreads();

        // ---- gates + publish + arrive (warp 0; R8-proven sequence)
        if (w == 0) {
            float sum = red[0][l];
#pragma unroll
            for (int q = 1; q < 8; q++) sum += red[q][l];
            float gv = sum + bias;
            if (is0) gv += sx[t] * wx;
            float fv = __shfl_sync(FULLMASK, gv, l + 8);
            float gg = __shfl_sync(FULLMASK, gv, l + 16);
            float ov = __shfl_sync(FULLMASK, gv, l + 24);
            if (l < 8) {
                float iv = sigfast(gv);
                float ff = sigfast(fv);
                float gt = tanhfast(gg);
                float oo = sigfast(ov);
                c = ff * c + iv * gt;
                float hn = oo * tanhfast(c);
                int hj = b * HPC + l;
                if (is0) {
                    g_h1ring[t & (D1 - 1)][hj] = hn;
                } else {
                    g_h2ring[t & 1][hj] = hn;
                    if (t == TT - 1) g_hfinal[hj] = hn;
                }
            }
            __syncwarp();
            if (l == 0) {
                __threadfence();    // order h stores before arrival
                atomicAdd((is0 ? g_barA : g_barB) + (b & 7) * PADC, 1u);
            }
        }
        // NOTE: no trailing __syncthreads needed: the next iteration's wait +
        // __syncthreads orders all warps before any buffer access, and warp 0
        // is the only writer of ring slots it republishes D1 (or 2) steps later.
        __syncthreads();
    }
}

// ---------- MLP head on final h2 ----------
__global__ void head_kernel(const float* __restrict__ w1, const float* __restrict__ b1,
                            const float* __restrict__ w2, const float* __restrict__ b2,
                            float* __restrict__ out)
{
    __shared__ float y1[32];
    const int tid = threadIdx.x, w = tid >> 5, l = tid & 31;
    for (int r = w; r < 20; r += 8) {
        float acc = 0.0f;
        for (int k = l; k < H; k += 32) acc += g_hfinal[k] * w1[r * H + k];
#pragma unroll
        for (int off = 16; off; off >>= 1) acc += __shfl_xor_sync(FULLMASK, acc, off);
        if (l == 0) y1[r] = acc + b1[r];
    }
    __syncthreads();
    if (tid == 0) {
        float o = b2[0];
#pragma unroll
        for (int r = 0; r < 20; r++) o += y1[r] * w2[r];
        out[0] = o;
    }
}

extern "C" void kernel_launch(void* const* d_in, const int* in_sizes, int n_in,
                              void* d_out, int out_size)
{
    const float* x    = (const float*)d_in[0];
    const float* wih0 = (const float*)d_in[1];
    const float* whh0 = (const float*)d_in[2];
    const float* bih0 = (const float*)d_in[3];
    const float* bhh0 = (const float*)d_in[4];
    const float* wih1 = (const float*)d_in[5];
    const float* whh1 = (const float*)d_in[6];
    const float* bih1 = (const float*)d_in[7];
    const float* bhh1 = (const float*)d_in[8];
    const float* w1   = (const float*)d_in[9];
    const float* b1   = (const float*)d_in[10];
    const float* w2   = (const float*)d_in[11];
    const float* b2   = (const float*)d_in[12];
    float* out = (float*)d_out;

    init_kernel<<<1, 256>>>();
    lstm2_kernel<<<NCTA, NTHREADS>>>(x, wih0, whh0, bih0, bhh0,
                                     wih1, whh1, bih1, bhh1);
    head_kernel<<<1, 256>>>(w1, b1, w2, b2, out);
}

// round 13
// speedup vs baseline: 1.1476x; 1.1476x over previous
#include <cuda_runtime.h>

#define TT 8192
#define H 512
#define NCTA_L 64      // CTAs per layer
#define NCTA 128       // total CTAs
#define NTHREADS 256
#define HPC 8          // h outputs per CTA
#define NCTR 16        // barrier counters (CTA bg -> counter bg&15; 8 arrivals each)
#define PADC 32        // 32 uints = one 128B line per counter
#define D1 4           // h1 ring depth
#define FULLMASK 0xffffffffu

// Static scratch (no allocations allowed)
__device__ float g_h1buf[D1][H];     // h1 exchange ring (hot 8KB)
__device__ float g_h2buf[2][H];      // h2 exchange ring
__device__ float g_hfinal[H];        // final h2
__device__ unsigned g_bar16[NCTR * PADC];   // 16 padded barrier counters

// ---------- helpers ----------
__device__ __forceinline__ unsigned long long pack2(float lo, float hi) {
    unsigned long long r;
    asm("mov.b64 %0,{%1,%2};" : "=l"(r) : "f"(lo), "f"(hi));
    return r;
}
__device__ __forceinline__ void unpack2(unsigned long long v, float& lo, float& hi) {
    asm("mov.b64 {%0,%1},%2;" : "=f"(lo), "=f"(hi) : "l"(v));
}
// packed fp32x2 FMA: 2 MACs per instruction (PTX-only on Blackwell)
__device__ __forceinline__ void fma2(unsigned long long& acc, unsigned long long a, unsigned long long b) {
    asm("fma.rn.f32x2 %0,%1,%2,%0;" : "+l"(acc) : "l"(a), "l"(b));
}
__device__ __forceinline__ float4 ldcg4(const float4* p) {
    float4 v;
    asm volatile("ld.global.cg.v4.f32 {%0,%1,%2,%3},[%4];"
                 : "=f"(v.x), "=f"(v.y), "=f"(v.z), "=f"(v.w) : "l"(p));
    return v;
}
__device__ __forceinline__ unsigned ldacq(const unsigned* p) {
    unsigned v;
    asm volatile("ld.acquire.gpu.u32 %0,[%1];" : "=r"(v) : "l"(p));
    return v;
}
__device__ __forceinline__ float tanhfast(float x) {
    float y; asm("tanh.approx.f32 %0,%1;" : "=f"(y) : "f"(x)); return y;
}
__device__ __forceinline__ float sigfast(float x) { return 0.5f * tanhfast(0.5f * x) + 0.5f; }

// ---------- init: reset barrier counters ----------
__global__ void init_kernel() {
    int t = threadIdx.x;
    if (t < NCTR * PADC) g_bar16[t] = 0u;
}

// ---------- fused superstep-pipelined 2-layer LSTM (R10 + lag-2 L1 + 16 ctrs) ----------
// 128 CTAs x 256 threads (single wave). CTAs [0,64): layer 0; [64,128): layer 1.
// Superstep s (0..TT+1): L0 computes h1(s) (s<TT); L1 computes h2(s-2) (s>=2).
// L1's input matvec W_ih1 . h1(s-1) runs in the superstep-s TAIL (after our
// arrival, overlapping peers' detect) and is carried in registers to s+1.
// CTA-internal layout (R8-proven): CTA owns 8 outputs -> 32 gate rows; warp w
// covers columns [64w,64w+64); lane l = gate row (0..7=i, 8..15=f, 16..23=g, 24..31=o).
__global__ void __launch_bounds__(NTHREADS, 1) lstm2_kernel(
    const float* __restrict__ x,
    const float* __restrict__ wih0, const float* __restrict__ whh0,
    const float* __restrict__ bih0, const float* __restrict__ bhh0,
    const float* __restrict__ wih1, const float* __restrict__ whh1,
    const float* __restrict__ bih1, const float* __restrict__ bhh1)
{
    const int tid = threadIdx.x;
    const int w = tid >> 5;
    const int l = tid & 31;
    const int bg = blockIdx.x;
    const bool is0 = bg < NCTA_L;
    const int b = is0 ? bg : (bg - NCTA_L);
    const int sec = l >> 3;
    const int j8 = l & 7;
    const int grow = sec * H + b * HPC + j8;

    __shared__ float red[8][33];
    __shared__ float sx[TT];
    if (is0) for (int i = tid; i < TT; i += NTHREADS) sx[i] = x[i];

    // recurrent weights -> registers (64 floats/thread)
    unsigned long long whh[32];
    {
        const float* wr = (is0 ? whh0 : whh1) + (size_t)grow * H + w * 64;
#pragma unroll
        for (int k = 0; k < 16; k++) {
            float4 v = *(const float4*)(wr + 4 * k);
            whh[2 * k] = pack2(v.x, v.y);
            whh[2 * k + 1] = pack2(v.z, v.w);
        }
    }
    // layer-1 input weights (L1 CTAs only)
    unsigned long long wihr[32];
    if (!is0) {
        const float* wr = wih1 + (size_t)grow * H + w * 64;
#pragma unroll
        for (int k = 0; k < 16; k++) {
            float4 v = *(const float4*)(wr + 4 * k);
            wihr[2 * k] = pack2(v.x, v.y);
            wihr[2 * k + 1] = pack2(v.z, v.w);
        }
    }
    const float bias = is0 ? (bih0[grow] + bhh0[grow]) : (bih1[grow] + bhh1[grow]);
    const float wx = is0 ? wih0[grow] : 0.0f;   // NC = 1
    float c = 0.0f;                              // cell state (lanes 0..7 of warp 0)
    unsigned long long xp0 = 0ull, xp1 = 0ull;   // L1 carried input partials
    __syncthreads();

    for (int s = 0; s <= TT + 1; s++) {
        // ---- barrier detect: everyone arrived s times (lanes 0..15 poll 16 ctrs)
        if (s > 0) {
            if (tid < 32) {
                const unsigned tgt = 8u * (unsigned)s;       // 8 CTAs per counter
                const unsigned* cp = &g_bar16[(l & 15) * PADC];
                for (;;) {
                    unsigned v = (l < 16) ? ldacq(cp) : tgt;
                    if (__all_sync(FULLMASK, v >= tgt)) break;
                }
            }
            __syncthreads();
        }

        const bool active = is0 ? (s < TT) : (s >= 2);

        // ---- critical mat-vec (ONE matvec for both layers now)
        unsigned long long a0 = 0ull, a1 = 0ull;
        if (active) {
            if (is0) {
                if (s > 0) {   // W_hh0 . h1(s-1)
                    const float4* hb = ((const float4*)g_h1buf[(s - 1) & (D1 - 1)]) + w * 16;
#pragma unroll
                    for (int k = 0; k < 16; k++) {
                        float4 hv = ldcg4(hb + k);
                        fma2(a0, whh[2 * k], pack2(hv.x, hv.y));
                        fma2(a1, whh[2 * k + 1], pack2(hv.z, hv.w));
                    }
                }
            } else {
                a0 = xp0; a1 = xp1;              // W_ih1 . h1(s-2) from the s-1 tail
                if (s > 2) {   // W_hh1 . h2(s-3)
                    const float4* hb = ((const float4*)g_h2buf[(s - 3) & 1]) + w * 16;
#pragma unroll
                    for (int k = 0; k < 16; k++) {
                        float4 hv = ldcg4(hb + k);
                        fma2(a0, whh[2 * k], pack2(hv.x, hv.y));
                        fma2(a1, whh[2 * k + 1], pack2(hv.z, hv.w));
                    }
                }
            }
        }
        float lo0, hi0, lo1, hi1;
        unpack2(a0, lo0, hi0);
        unpack2(a1, lo1, hi1);
        red[w][l] = (lo0 + hi0) + (lo1 + hi1);
        __syncthreads();

        // ---- gates + publish + arrive (warp 0; R8-proven sequence)
        if (w == 0) {
            if (active) {
                float sum = red[0][l];
#pragma unroll
                for (int q = 1; q < 8; q++) sum += red[q][l];
                float gv = sum + bias;
                if (is0) gv += sx[s] * wx;
                float fv = __shfl_sync(FULLMASK, gv, l + 8);
                float gg = __shfl_sync(FULLMASK, gv, l + 16);
                float ov = __shfl_sync(FULLMASK, gv, l + 24);
                if (l < 8) {
                    float iv = sigfast(gv);
                    float ff = sigfast(fv);
                    float gt = tanhfast(gg);
                    float oo = sigfast(ov);
                    c = ff * c + iv * gt;
                    float hn = oo * tanhfast(c);
                    int hj = b * HPC + l;
                    if (is0) {
                        g_h1buf[s & (D1 - 1)][hj] = hn;      // publish h1(s)
                    } else {
                        g_h2buf[(s - 2) & 1][hj] = hn;       // publish h2(s-2)
                        if (s == TT + 1) g_hfinal[hj] = hn;
                    }
                }
            }
            __syncwarp();
            if (l == 0 && s <= TT) {
                __threadfence();                              // order stores
                atomicAdd(&g_bar16[(bg & 15) * PADC], 1u);   // arrive
            }
        }

        // ---- tail (L1, all warps): xp = W_ih1 . h1(s-1), for superstep s+1.
        // h1(s-1) is barrier-guaranteed since superstep s; runs after our
        // arrival, overlapped with peers' detect. Ring depth 4 + straggler
        // argument make the slot overwrite-safe.
        if (!is0 && s >= 1 && s <= TT) {
            const float4* hb = ((const float4*)g_h1buf[(s - 1) & (D1 - 1)]) + w * 16;
            xp0 = 0ull; xp1 = 0ull;
#pragma unroll
            for (int k = 0; k < 16; k++) {
                float4 hv = ldcg4(hb + k);
                fma2(xp0, wihr[2 * k], pack2(hv.x, hv.y));
                fma2(xp1, wihr[2 * k + 1], pack2(hv.z, hv.w));
            }
        }
        __syncthreads();   // protect red[] reuse (R12 autopsy: this sync is load-bearing)
    }
}

// ---------- MLP head on final h2 ----------
__global__ void head_kernel(const float* __restrict__ w1, const float* __restrict__ b1,
                            const float* __restrict__ w2, const float* __restrict__ b2,
                            float* __restrict__ out)
{
    __shared__ float y1[32];
    const int tid = threadIdx.x, w = tid >> 5, l = tid & 31;
    for (int r = w; r < 20; r += 8) {
        float acc = 0.0f;
        for (int k = l; k < H; k += 32) acc += g_hfinal[k] * w1[r * H + k];
#pragma unroll
        for (int off = 16; off; off >>= 1) acc += __shfl_xor_sync(FULLMASK, acc, off);
        if (l == 0) y1[r] = acc + b1[r];
    }
    __syncthreads();
    if (tid == 0) {
        float o = b2[0];
#pragma unroll
        for (int r = 0; r < 20; r++) o += y1[r] * w2[r];
        out[0] = o;
    }
}

extern "C" void kernel_launch(void* const* d_in, const int* in_sizes, int n_in,
                              void* d_out, int out_size)
{
    const float* x    = (const float*)d_in[0];
    const float* wih0 = (const float*)d_in[1];
    const float* whh0 = (const float*)d_in[2];
    const float* bih0 = (const float*)d_in[3];
    const float* bhh0 = (const float*)d_in[4];
    const float* wih1 = (const float*)d_in[5];
    const float* whh1 = (const float*)d_in[6];
    const float* bih1 = (const float*)d_in[7];
    const float* bhh1 = (const float*)d_in[8];
    const float* w1   = (const float*)d_in[9];
    const float* b1   = (const float*)d_in[10];
    const float* w2   = (const float*)d_in[11];
    const float* b2   = (const float*)d_in[12];
    float* out = (float*)d_out;

    init_kernel<<<1, 512>>>();
    lstm2_kernel<<<NCTA, NTHREADS>>>(x, wih0, whh0, bih0, bhh0,
                                     wih1, whh1, bih1, bhh1);
    head_kernel<<<1, 256>>>(w1, b1, w2, b2, out);
}

// round 14
// speedup vs baseline: 1.7815x; 1.5523x over previous
#include <cuda_runtime.h>

#define TT 8192
#define H 512
#define NCTA_L 64      // CTAs per layer
#define NCTA 128       // total CTAs
#define NTHREADS 256
#define HPC 8          // h outputs per CTA
#define NCTR 16        // barrier counters (CTA bg -> counter bg&15; 8 arrivals each)
#define PADC 32        // 32 uints = one 128B line per counter
#define D1 4           // h1 ring depth
#define FULLMASK 0xffffffffu

typedef unsigned long long u64;

// Static scratch (no allocations allowed)
__device__ float g_h1buf[D1][H];     // h1 exchange ring (hot 8KB)
__device__ float g_h2buf[2][H];      // h2 exchange ring
__device__ float g_hfinal[H];        // final h2
__device__ unsigned g_bar16[NCTR * PADC];   // 16 padded barrier counters

// ---------- helpers ----------
__device__ __forceinline__ u64 pack2(float lo, float hi) {
    u64 r;
    asm("mov.b64 %0,{%1,%2};" : "=l"(r) : "f"(lo), "f"(hi));
    return r;
}
__device__ __forceinline__ void unpack2(u64 v, float& lo, float& hi) {
    asm("mov.b64 {%0,%1},%2;" : "=f"(lo), "=f"(hi) : "l"(v));
}
// packed fp32x2 FMA: 2 MACs per instruction (PTX-only on Blackwell)
__device__ __forceinline__ void fma2(u64& acc, u64 a, u64 b) {
    asm("fma.rn.f32x2 %0,%1,%2,%0;" : "+l"(acc) : "l"(a), "l"(b));
}
__device__ __forceinline__ float4 ldcg4(const float4* p) {
    float4 v;
    asm volatile("ld.global.cg.v4.f32 {%0,%1,%2,%3},[%4];"
                 : "=f"(v.x), "=f"(v.y), "=f"(v.z), "=f"(v.w) : "l"(p));
    return v;
}
__device__ __forceinline__ unsigned ldacq(const unsigned* p) {
    unsigned v;
    asm volatile("ld.acquire.gpu.u32 %0,[%1];" : "=r"(v) : "l"(p));
    return v;
}
__device__ __forceinline__ float tanhfast(float x) {
    float y; asm("tanh.approx.f32 %0,%1;" : "=f"(y) : "f"(x)); return y;
}
__device__ __forceinline__ float sigfast(float x) { return 0.5f * tanhfast(0.5f * x) + 0.5f; }

// warp-cooperative: lanes 0..15 fetch the warp's 64-float h chunk with ONE
// coalesced .cg load (2 cache lines, 2 wavefronts) into the warp's smem strip.
// 8x fewer L2 requests than 16 same-address broadcast loads.
__device__ __forceinline__ void stage64(const float* ringchunk, float* strip, int l) {
    __syncwarp();                      // strip reuse safety
    if (l < 16) {
        float4 v = ldcg4(((const float4*)ringchunk) + l);
        *(float4*)(strip + 4 * l) = v;
    }
    __syncwarp();
}
// matvec from the staged strip (broadcast LDS, conflict-free)
__device__ __forceinline__ void matvec_smem(const float* strip, const u64* wreg,
                                            u64& a0, u64& a1) {
    const u64* hp = (const u64*)strip;
#pragma unroll
    for (int k = 0; k < 16; k++) {
        fma2(a0, wreg[2 * k],     hp[2 * k]);
        fma2(a1, wreg[2 * k + 1], hp[2 * k + 1]);
    }
}

// ---------- init: reset barrier counters ----------
__global__ void init_kernel() {
    int t = threadIdx.x;
    if (t < NCTR * PADC) g_bar16[t] = 0u;
}

// ---------- fused superstep-pipelined 2-layer LSTM (R13 + staged loads) ----------
// 128 CTAs x 256 threads (single wave). CTAs [0,64): layer 0; [64,128): layer 1.
// Superstep s (0..TT+1): L0 computes h1(s) (s<TT); L1 computes h2(s-2) (s>=2).
// L1's input matvec W_ih1 . h1(s-1) runs in the superstep-s TAIL and is carried
// in registers to s+1.
// CTA-internal layout (R8-proven): CTA owns 8 outputs -> 32 gate rows; warp w
// covers columns [64w,64w+64); lane l = gate row (0..7=i, 8..15=f, 16..23=g, 24..31=o).
__global__ void __launch_bounds__(NTHREADS, 1) lstm2_kernel(
    const float* __restrict__ x,
    const float* __restrict__ wih0, const float* __restrict__ whh0,
    const float* __restrict__ bih0, const float* __restrict__ bhh0,
    const float* __restrict__ wih1, const float* __restrict__ whh1,
    const float* __restrict__ bih1, const float* __restrict__ bhh1)
{
    const int tid = threadIdx.x;
    const int w = tid >> 5;
    const int l = tid & 31;
    const int bg = blockIdx.x;
    const bool is0 = bg < NCTA_L;
    const int b = is0 ? bg : (bg - NCTA_L);
    const int sec = l >> 3;
    const int j8 = l & 7;
    const int grow = sec * H + b * HPC + j8;

    __shared__ float red[8][33];
    __shared__ float hstage[8][64];    // per-warp staged h chunk
    __shared__ float sx[TT];
    if (is0) for (int i = tid; i < TT; i += NTHREADS) sx[i] = x[i];

    // recurrent weights -> registers (64 floats/thread)
    u64 whh[32];
    {
        const float* wr = (is0 ? whh0 : whh1) + (size_t)grow * H + w * 64;
#pragma unroll
        for (int k = 0; k < 16; k++) {
            float4 v = *(const float4*)(wr + 4 * k);
            whh[2 * k] = pack2(v.x, v.y);
            whh[2 * k + 1] = pack2(v.z, v.w);
        }
    }
    // layer-1 input weights (L1 CTAs only)
    u64 wihr[32];
    if (!is0) {
        const float* wr = wih1 + (size_t)grow * H + w * 64;
#pragma unroll
        for (int k = 0; k < 16; k++) {
            float4 v = *(const float4*)(wr + 4 * k);
            wihr[2 * k] = pack2(v.x, v.y);
            wihr[2 * k + 1] = pack2(v.z, v.w);
        }
    }
    const float bias = is0 ? (bih0[grow] + bhh0[grow]) : (bih1[grow] + bhh1[grow]);
    const float wx = is0 ? wih0[grow] : 0.0f;   // NC = 1
    float c = 0.0f;                              // cell state (lanes 0..7 of warp 0)
    u64 xp0 = 0ull, xp1 = 0ull;                  // L1 carried input partials
    __syncthreads();

    for (int s = 0; s <= TT + 1; s++) {
        // ---- barrier detect: everyone arrived s times (lanes 0..15 poll 16 ctrs)
        if (s > 0) {
            if (tid < 32) {
                const unsigned tgt = 8u * (unsigned)s;       // 8 CTAs per counter
                const unsigned* cp = &g_bar16[(l & 15) * PADC];
                for (;;) {
                    unsigned v = (l < 16) ? ldacq(cp) : tgt;
                    if (__all_sync(FULLMASK, v >= tgt)) break;
                }
            }
            __syncthreads();
        }

        const bool active = is0 ? (s < TT) : (s >= 2);

        // ---- critical mat-vec (ONE matvec for both layers; staged loads)
        u64 a0 = 0ull, a1 = 0ull;
        if (active) {
            if (is0) {
                if (s > 0) {   // W_hh0 . h1(s-1)
                    stage64(g_h1buf[(s - 1) & (D1 - 1)] + w * 64, hstage[w], l);
                    matvec_smem(hstage[w], whh, a0, a1);
                }
            } else {
                a0 = xp0; a1 = xp1;              // W_ih1 . h1(s-2) from the s-1 tail
                if (s > 2) {   // W_hh1 . h2(s-3)
                    stage64(g_h2buf[(s - 3) & 1] + w * 64, hstage[w], l);
                    matvec_smem(hstage[w], whh, a0, a1);
                }
            }
        }
        float lo0, hi0, lo1, hi1;
        unpack2(a0, lo0, hi0);
        unpack2(a1, lo1, hi1);
        red[w][l] = (lo0 + hi0) + (lo1 + hi1);
        __syncthreads();

        // ---- gates + publish + arrive (warp 0; R8-proven sequence)
        if (w == 0) {
            if (active) {
                float sum = red[0][l];
#pragma unroll
                for (int q = 1; q < 8; q++) sum += red[q][l];
                float gv = sum + bias;
                if (is0) gv += sx[s] * wx;
                float fv = __shfl_sync(FULLMASK, gv, l + 8);
                float gg = __shfl_sync(FULLMASK, gv, l + 16);
                float ov = __shfl_sync(FULLMASK, gv, l + 24);
                if (l < 8) {
                    float iv = sigfast(gv);
                    float ff = sigfast(fv);
                    float gt = tanhfast(gg);
                    float oo = sigfast(ov);
                    c = ff * c + iv * gt;
                    float hn = oo * tanhfast(c);
                    int hj = b * HPC + l;
                    if (is0) {
                        g_h1buf[s & (D1 - 1)][hj] = hn;      // publish h1(s)
                    } else {
                        g_h2buf[(s - 2) & 1][hj] = hn;       // publish h2(s-2)
                        if (s == TT + 1) g_hfinal[hj] = hn;
                    }
                }
            }
            __syncwarp();
            if (l == 0 && s <= TT) {
                __threadfence();                              // order stores
                atomicAdd(&g_bar16[(bg & 15) * PADC], 1u);   // arrive
            }
        }

        // ---- tail (L1, all warps): xp = W_ih1 . h1(s-1), for superstep s+1.
        // h1(s-1) is barrier-guaranteed since superstep s; runs after our
        // arrival, overlapped with peers' detect.
        if (!is0 && s >= 1 && s <= TT) {
            stage64(g_h1buf[(s - 1) & (D1 - 1)] + w * 64, hstage[w], l);
            xp0 = 0ull; xp1 = 0ull;
            matvec_smem(hstage[w], wihr, xp0, xp1);
        }
        __syncthreads();   // protect red[]/hstage reuse (load-bearing, R12 autopsy)
    }
}

// ---------- MLP head on final h2 ----------
__global__ void head_kernel(const float* __restrict__ w1, const float* __restrict__ b1,
                            const float* __restrict__ w2, const float* __restrict__ b2,
                            float* __restrict__ out)
{
    __shared__ float y1[32];
    const int tid = threadIdx.x, w = tid >> 5, l = tid & 31;
    for (int r = w; r < 20; r += 8) {
        float acc = 0.0f;
        for (int k = l; k < H; k += 32) acc += g_hfinal[k] * w1[r * H + k];
#pragma unroll
        for (int off = 16; off; off >>= 1) acc += __shfl_xor_sync(FULLMASK, acc, off);
        if (l == 0) y1[r] = acc + b1[r];
    }
    __syncthreads();
    if (tid == 0) {
        float o = b2[0];
#pragma unroll
        for (int r = 0; r < 20; r++) o += y1[r] * w2[r];
        out[0] = o;
    }
}

extern "C" void kernel_launch(void* const* d_in, const int* in_sizes, int n_in,
                              void* d_out, int out_size)
{
    const float* x    = (const float*)d_in[0];
    const float* wih0 = (const float*)d_in[1];
    const float* whh0 = (const float*)d_in[2];
    const float* bih0 = (const float*)d_in[3];
    const float* bhh0 = (const float*)d_in[4];
    const float* wih1 = (const float*)d_in[5];
    const float* whh1 = (const float*)d_in[6];
    const float* bih1 = (const float*)d_in[7];
    const float* bhh1 = (const float*)d_in[8];
    const float* w1   = (const float*)d_in[9];
    const float* b1   = (const float*)d_in[10];
    const float* w2   = (const float*)d_in[11];
    const float* b2   = (const float*)d_in[12];
    float* out = (float*)d_out;

    init_kernel<<<1, 512>>>();
    lstm2_kernel<<<NCTA, NTHREADS>>>(x, wih0, whh0, bih0, bhh0,
                                     wih1, whh1, bih1, bhh1);
    head_kernel<<<1, 256>>>(w1, b1, w2, b2, out);
}